// round 13
// baseline (speedup 1.0000x reference)
#include <cuda_runtime.h>
#include <cuda_bf16.h>
#include <cstdint>

#define DIM   256
#define HIST  200
#define VROWS 100000
#define EPSF  1e-12f
#define ROWB  528            // smem row stride bytes: (256+8) bf16

// ---------------- persistent device scratch ----------------
__device__ __nv_bfloat16 g_vnorm[(size_t)VROWS * DIM];  // max-norm venue rows, bf16
__device__ __nv_bfloat16 g_Bt[DIM * DIM];               // W1^T  (Bt[n][k] = W1[k][n])
__device__ __nv_bfloat16 g_Cb[HIST * DIM];              // P@W2 + bias, bf16
__device__ uint32_t      g_TV[(size_t)VROWS * DIM];     // lo16=T bf16, hi16=vnorm bf16

// ---------------- helpers ----------------
__device__ __forceinline__ uint32_t smem_u32(const void* p) {
    uint32_t a;
    asm("{ .reg .u64 t; cvta.to.shared.u64 t, %1; cvt.u32.u64 %0, t; }" : "=r"(a) : "l"(p));
    return a;
}
__device__ __forceinline__ float tanh_fast(float x) {
    float y; asm("tanh.approx.f32 %0, %1;" : "=f"(y) : "f"(x)); return y;
}
__device__ __forceinline__ void ldsm_x4(uint32_t* r, uint32_t addr) {
    asm volatile("ldmatrix.sync.aligned.m8n8.x4.shared.b16 {%0,%1,%2,%3}, [%4];"
                 : "=r"(r[0]), "=r"(r[1]), "=r"(r[2]), "=r"(r[3]) : "r"(addr));
}
__device__ __forceinline__ void mma_bf16(float* d, const uint32_t* a,
                                         uint32_t b0, uint32_t b1) {
    asm volatile(
        "mma.sync.aligned.m16n8k16.row.col.f32.bf16.bf16.f32 "
        "{%0,%1,%2,%3}, {%4,%5,%6,%7}, {%8,%9}, {%0,%1,%2,%3};"
        : "+f"(d[0]), "+f"(d[1]), "+f"(d[2]), "+f"(d[3])
        : "r"(a[0]), "r"(a[1]), "r"(a[2]), "r"(a[3]), "r"(b0), "r"(b1));
}
__device__ __forceinline__ void cp16(uint32_t dst, const void* src) {
    asm volatile("cp.async.cg.shared.global [%0], [%1], 16;" :: "r"(dst), "l"(src));
}
__device__ __forceinline__ void cp_commit() { asm volatile("cp.async.commit_group;" ::: "memory"); }
__device__ __forceinline__ void cp_wait0()  { asm volatile("cp.async.wait_group 0;" ::: "memory"); }

// ---------------- merged precompute: normalize (warp/row) + Bt + C(bf16) ----------------
__global__ void precompute_kernel(const float* __restrict__ venue, int rows, int nb,
                                  const float* __restrict__ W1,
                                  const float* __restrict__ P,
                                  const float* __restrict__ W2,
                                  const float* __restrict__ bias) {
    const int bid = blockIdx.x;
    if (bid < nb) {
        // ---- normalize 8 venue rows per CTA (one warp per row) ----
        const int row  = bid * 8 + (threadIdx.x >> 5);
        const int lane = threadIdx.x & 31;
        if (row >= rows) return;
        const float4* src = reinterpret_cast<const float4*>(venue + (size_t)row * DIM) + lane * 2;
        float4 x0 = src[0], x1 = src[1];
        float ss = x0.x*x0.x + x0.y*x0.y + x0.z*x0.z + x0.w*x0.w
                 + x1.x*x1.x + x1.y*x1.y + x1.z*x1.z + x1.w*x1.w;
        #pragma unroll
        for (int o = 16; o > 0; o >>= 1) ss += __shfl_xor_sync(0xffffffffu, ss, o);
        const float sc = fminf(1.0f, 1.0f / fmaxf(sqrtf(ss), EPSF));   // torch max_norm=1
        __nv_bfloat162 b0 = __floats2bfloat162_rn(x0.x*sc, x0.y*sc);
        __nv_bfloat162 b1 = __floats2bfloat162_rn(x0.z*sc, x0.w*sc);
        __nv_bfloat162 b2 = __floats2bfloat162_rn(x1.x*sc, x1.y*sc);
        __nv_bfloat162 b3 = __floats2bfloat162_rn(x1.z*sc, x1.w*sc);
        uint4 o4;
        o4.x = *reinterpret_cast<uint32_t*>(&b0); o4.y = *reinterpret_cast<uint32_t*>(&b1);
        o4.z = *reinterpret_cast<uint32_t*>(&b2); o4.w = *reinterpret_cast<uint32_t*>(&b3);
        reinterpret_cast<uint4*>(g_vnorm + (size_t)row * DIM)[lane] = o4;
    } else if (bid < nb + DIM) {
        // ---- Bt row ----
        const int n = bid - nb, k = threadIdx.x;
        g_Bt[n * DIM + k] = __float2bfloat16(W1[k * DIM + n]);
    } else {
        // ---- C row (bf16) ----
        __shared__ float sP[DIM];
        const int h = bid - nb - DIM, d = threadIdx.x;
        sP[d] = P[h * DIM + d];
        __syncthreads();
        float acc = 0.f;
        #pragma unroll 16
        for (int k = 0; k < DIM; ++k) acc = fmaf(sP[k], W2[k * DIM + d], acc);
        g_Cb[h * DIM + d] = __float2bfloat16(acc + bias[h * DIM + d]);
    }
}

// ---------------- TV = pack(vnorm @ W1, vnorm) — R8 proven form, occ 3 ----------------
#define GSM_A 0
#define GSM_B 33792
#define GSM_BYTES 67584

__global__ __launch_bounds__(256, 3)
void gemm_TV_kernel(int rows) {
    extern __shared__ __align__(16) char sm[];
    const int tid = threadIdx.x, lane = tid & 31, warp = tid >> 5;
    const int M0 = blockIdx.x * 64;
    const uint32_t smA = smem_u32(sm + GSM_A);
    const uint32_t smB = smem_u32(sm + GSM_B);

    // ---- A tile (64 rows of bf16 vnorm) + B chunk 0, all via cp.async ----
    #pragma unroll
    for (int s = 0; s < 8; ++s) {
        const int i = tid + s * 256;            // 0..2047
        const int row = i >> 5, j = i & 31;
        const int gr = M0 + row;
        if (gr < rows)
            cp16(smA + row * ROWB + j * 16,
                 reinterpret_cast<const char*>(g_vnorm) + (size_t)gr * DIM * 2 + j * 16);
        else
            *reinterpret_cast<uint4*>(sm + GSM_A + row * ROWB + j * 16) = make_uint4(0,0,0,0);
    }
    {
        const char* src = reinterpret_cast<const char*>(g_Bt);
        #pragma unroll
        for (int s = 0; s < 8; ++s) {
            const int i = tid + s * 256;
            const int row = i >> 5, j = i & 31;
            cp16(smB + row * ROWB + j * 16, src + row * 512 + j * 16);
        }
    }
    cp_commit();

    // warp tile 32x16: mgrp = warp>>2 (row half), ngrp = warp&3 (16-col group)
    const int qr = lane >> 2, qc = lane & 3;
    const int mgrp = warp >> 2, ngrp = warp & 3;
    const uint32_t aAddr = smA + (uint32_t)((mgrp * 32 + (lane & 15)) * ROWB + (lane >> 4) * 16);
    const uint32_t bAddr = smB + (uint32_t)((ngrp * 16 + (lane & 7) + ((lane >> 4) & 1) * 8) * ROWB
                                            + ((lane >> 3) & 1) * 16);

    #pragma unroll 1
    for (int chunk = 0; chunk < 4; ++chunk) {
        cp_wait0();
        __syncthreads();       // A + current B chunk resident

        float acc[2][2][4];
        #pragma unroll
        for (int mt = 0; mt < 2; ++mt)
            #pragma unroll
            for (int nt = 0; nt < 2; ++nt)
                #pragma unroll
                for (int i = 0; i < 4; ++i) acc[mt][nt][i] = 0.f;

        #pragma unroll 4
        for (int ks = 0; ks < 16; ++ks) {
            uint32_t af[2][4], bf[4];
            ldsm_x4(af[0], aAddr + ks * 32);
            ldsm_x4(af[1], aAddr + 16 * ROWB + ks * 32);
            ldsm_x4(bf, bAddr + ks * 32);
            #pragma unroll
            for (int mt = 0; mt < 2; ++mt)
                #pragma unroll
                for (int nt = 0; nt < 2; ++nt)
                    mma_bf16(acc[mt][nt], af[mt], bf[nt * 2], bf[nt * 2 + 1]);
        }
        __syncthreads();       // all warps done reading B before refill

        if (chunk < 3) {
            const char* src = reinterpret_cast<const char*>(g_Bt + (chunk + 1) * 64 * DIM);
            #pragma unroll
            for (int s = 0; s < 8; ++s) {
                const int i = tid + s * 256;
                const int row = i >> 5, j = i & 31;
                cp16(smB + row * ROWB + j * 16, src + row * 512 + j * 16);
            }
            cp_commit();
        }

        // ---- pack T(bf16) + vnorm(bf16 from smem A) -> g_TV; overlaps B refill ----
        #pragma unroll
        for (int mt = 0; mt < 2; ++mt) {
            const int lr0 = mgrp * 32 + mt * 16 + qr;
            #pragma unroll
            for (int nt = 0; nt < 2; ++nt) {
                const int col = chunk * 64 + ngrp * 16 + nt * 8 + 2 * qc;
                #pragma unroll
                for (int half = 0; half < 2; ++half) {
                    const int r0 = M0 + lr0 + half * 8;
                    if (r0 < rows) {
                        const uint32_t hh = *reinterpret_cast<const uint32_t*>(
                            sm + GSM_A + (lr0 + half * 8) * ROWB + col * 2);
                        __nv_bfloat162 tp = __floats2bfloat162_rn(
                            acc[mt][nt][half * 2 + 0], acc[mt][nt][half * 2 + 1]);
                        const uint32_t tpu = *reinterpret_cast<uint32_t*>(&tp);
                        uint2 st;
                        st.x = __byte_perm(tpu, hh, 0x5410);   // {T_lo, v_lo}
                        st.y = __byte_perm(tpu, hh, 0x7632);   // {T_hi, v_hi}
                        *reinterpret_cast<uint2*>(g_TV + (size_t)r0 * DIM + col) = st;
                    }
                }
            }
        }
    }
}

// ---------------- main kernel: 128 thr, 2 items/CTA sharing C (bf16), 2 cols/thread ----------------
__global__ __launch_bounds__(128)
void geo_main_kernel(const int* __restrict__ batch_u,
                     const int* __restrict__ batch_v,
                     const int* __restrict__ batch_history,
                     const float* __restrict__ user_emb,
                     const float* __restrict__ venue_emb,
                     const float* __restrict__ a_ptr,
                     float* __restrict__ out) {
    __shared__ int   sidx[2 * HIST];
    __shared__ float sred[12];
    __shared__ float sbc[2][3];

    const int bx = blockIdx.x, tid = threadIdx.x, lane = tid & 31, warp = tid >> 5;
    #pragma unroll
    for (int i = tid; i < 2 * HIST; i += 128)
        sidx[i] = batch_history[bx * 2 * HIST + i] << 8;   // pre-shifted row offsets
    __syncthreads();

    const int d0 = tid * 2;
    float den0a = 0.f, num0a = 0.f, den0b = 0.f, num0b = 0.f;   // item 0, cols d0/d0+1
    float den1a = 0.f, num1a = 0.f, den1b = 0.f, num1b = 0.f;   // item 1

    #pragma unroll 1
    for (int rb = 0; rb < HIST; rb += 8) {
        #pragma unroll
        for (int i = 0; i < 8; ++i) {
            const int r = rb + i;
            // one bf16x2 C load shared by both items
            const uint32_t cc = __ldg(reinterpret_cast<const uint32_t*>(g_Cb + r * DIM + d0));
            const float c0 = __uint_as_float(cc << 16);
            const float c1 = __uint_as_float(cc & 0xffff0000u);

            const uint2 tv0 = __ldg(reinterpret_cast<const uint2*>(
                g_TV + ((uint32_t)sidx[r] + d0)));
            const uint2 tv1 = __ldg(reinterpret_cast<const uint2*>(
                g_TV + ((uint32_t)sidx[HIST + r] + d0)));

            const float e0a = __expf(tanh_fast(__uint_as_float(tv0.x << 16) + c0));
            const float e0b = __expf(tanh_fast(__uint_as_float(tv0.y << 16) + c1));
            const float e1a = __expf(tanh_fast(__uint_as_float(tv1.x << 16) + c0));
            const float e1b = __expf(tanh_fast(__uint_as_float(tv1.y << 16) + c1));
            den0a += e0a;  den0b += e0b;  den1a += e1a;  den1b += e1b;
            num0a = fmaf(e0a, __uint_as_float(tv0.x & 0xffff0000u), num0a);
            num0b = fmaf(e0b, __uint_as_float(tv0.y & 0xffff0000u), num0b);
            num1a = fmaf(e1a, __uint_as_float(tv1.x & 0xffff0000u), num1a);
            num1b = fmaf(e1b, __uint_as_float(tv1.y & 0xffff0000u), num1b);
        }
    }

    // ---- per item: l = num/den + a; score = || l2n(u) + l2n(l) - l2n(v) || ----
    const float a_val = a_ptr[0];
    float lva[2], lvb[2];
    lva[0] = num0a / den0a + a_val;  lvb[0] = num0b / den0b + a_val;
    lva[1] = num1a / den1a + a_val;  lvb[1] = num1b / den1b + a_val;

    float2 uv[2], vv[2];
    #pragma unroll
    for (int g = 0; g < 2; ++g) {
        const int b = bx * 2 + g;
        uv[g] = __ldg(reinterpret_cast<const float2*>(user_emb  + (size_t)batch_u[b] * DIM + d0));
        vv[g] = __ldg(reinterpret_cast<const float2*>(venue_emb + (size_t)batch_v[b] * DIM + d0));
        float su = uv[g].x*uv[g].x + uv[g].y*uv[g].y;
        float sv = vv[g].x*vv[g].x + vv[g].y*vv[g].y;
        float sl = lva[g]*lva[g] + lvb[g]*lvb[g];
        #pragma unroll
        for (int o = 16; o > 0; o >>= 1) {
            su += __shfl_xor_sync(0xffffffffu, su, o);
            sv += __shfl_xor_sync(0xffffffffu, sv, o);
            sl += __shfl_xor_sync(0xffffffffu, sl, o);
        }
        if (lane == 0) { sred[warp] = su; sred[4 + warp] = sv; sred[8 + warp] = sl; }
        __syncthreads();
        if (tid == 0) {
            float tu = 0.f, tv2 = 0.f, tl = 0.f;
            #pragma unroll
            for (int w = 0; w < 4; ++w) { tu += sred[w]; tv2 += sred[4 + w]; tl += sred[8 + w]; }
            sbc[g][0] = 1.f / fmaxf(sqrtf(tu), EPSF);
            sbc[g][1] = 1.f / fmaxf(sqrtf(tv2), EPSF);
            sbc[g][2] = 1.f / fmaxf(sqrtf(tl), EPSF);
        }
        __syncthreads();
    }
    #pragma unroll
    for (int g = 0; g < 2; ++g) {
        const float s0 = uv[g].x * sbc[g][0] + lva[g] * sbc[g][2] - vv[g].x * sbc[g][1];
        const float s1 = uv[g].y * sbc[g][0] + lvb[g] * sbc[g][2] - vv[g].y * sbc[g][1];
        float ssq = s0 * s0 + s1 * s1;
        #pragma unroll
        for (int o = 16; o > 0; o >>= 1) ssq += __shfl_xor_sync(0xffffffffu, ssq, o);
        if (lane == 0) sred[g * 4 + warp] = ssq;
    }
    __syncthreads();
    if (tid < 2) {
        float tot = 0.f;
        #pragma unroll
        for (int w = 0; w < 4; ++w) tot += sred[tid * 4 + w];
        out[bx * 2 + tid] = sqrtf(tot);
    }
}

// ---------------- harness entry ----------------
extern "C" void kernel_launch(void* const* d_in, const int* in_sizes, int n_in,
                              void* d_out, int out_size) {
    const int*   batch_u       = (const int*)d_in[0];
    const int*   batch_v       = (const int*)d_in[1];
    const int*   batch_history = (const int*)d_in[2];
    const float* user_emb      = (const float*)d_in[5];
    const float* venue_emb     = (const float*)d_in[6];
    const float* W1            = (const float*)d_in[7];
    const float* W2            = (const float*)d_in[8];
    const float* P             = (const float*)d_in[9];
    const float* bias          = (const float*)d_in[10];
    const float* a             = (const float*)d_in[11];
    float* out = (float*)d_out;

    const int B = in_sizes[0];
    int rows = in_sizes[6] / DIM;
    if (rows > VROWS) rows = VROWS;
    const int nb = (rows + 7) / 8;

    cudaFuncSetAttribute(gemm_TV_kernel,
                         cudaFuncAttributeMaxDynamicSharedMemorySize, GSM_BYTES);

    precompute_kernel<<<nb + DIM + HIST, 256>>>(venue_emb, rows, nb, W1, P, W2, bias);
    gemm_TV_kernel<<<(rows + 63) / 64, 256, GSM_BYTES>>>(rows);
    geo_main_kernel<<<B / 2, 128>>>(batch_u, batch_v, batch_history,
                                    user_emb, venue_emb, a, out);
}

// round 14
// speedup vs baseline: 1.0557x; 1.0557x over previous
#include <cuda_runtime.h>
#include <cuda_bf16.h>
#include <cstdint>

#define DIM   256
#define HIST  200
#define VROWS 100000
#define EPSF  1e-12f
#define ROWB  528            // smem row stride bytes: (256+8) bf16

// ---------------- persistent device scratch ----------------
__device__ __nv_bfloat16 g_vnorm[(size_t)VROWS * DIM];  // max-norm venue rows, bf16
__device__ __nv_bfloat16 g_Bt[DIM * DIM];               // W1^T  (Bt[n][k] = W1[k][n])
__device__ __nv_bfloat16 g_Cb[HIST * DIM];              // P@W2 + bias, bf16
__device__ uint32_t      g_TV[(size_t)VROWS * DIM];     // lo16=T bf16, hi16=vnorm bf16

// ---------------- helpers ----------------
__device__ __forceinline__ uint32_t smem_u32(const void* p) {
    uint32_t a;
    asm("{ .reg .u64 t; cvta.to.shared.u64 t, %1; cvt.u32.u64 %0, t; }" : "=r"(a) : "l"(p));
    return a;
}
__device__ __forceinline__ float tanh_fast(float x) {
    float y; asm("tanh.approx.f32 %0, %1;" : "=f"(y) : "f"(x)); return y;
}
__device__ __forceinline__ void ldsm_x4(uint32_t* r, uint32_t addr) {
    asm volatile("ldmatrix.sync.aligned.m8n8.x4.shared.b16 {%0,%1,%2,%3}, [%4];"
                 : "=r"(r[0]), "=r"(r[1]), "=r"(r[2]), "=r"(r[3]) : "r"(addr));
}
__device__ __forceinline__ void mma_bf16(float* d, const uint32_t* a,
                                         uint32_t b0, uint32_t b1) {
    asm volatile(
        "mma.sync.aligned.m16n8k16.row.col.f32.bf16.bf16.f32 "
        "{%0,%1,%2,%3}, {%4,%5,%6,%7}, {%8,%9}, {%0,%1,%2,%3};"
        : "+f"(d[0]), "+f"(d[1]), "+f"(d[2]), "+f"(d[3])
        : "r"(a[0]), "r"(a[1]), "r"(a[2]), "r"(a[3]), "r"(b0), "r"(b1));
}
__device__ __forceinline__ void cp16(uint32_t dst, const void* src) {
    asm volatile("cp.async.cg.shared.global [%0], [%1], 16;" :: "r"(dst), "l"(src));
}
__device__ __forceinline__ void cp_commit() { asm volatile("cp.async.commit_group;" ::: "memory"); }
__device__ __forceinline__ void cp_wait0()  { asm volatile("cp.async.wait_group 0;" ::: "memory"); }

// ---------------- merged precompute: normalize (warp/row) + Bt + C(bf16) ----------------
__global__ void precompute_kernel(const float* __restrict__ venue, int rows, int nb,
                                  const float* __restrict__ W1,
                                  const float* __restrict__ P,
                                  const float* __restrict__ W2,
                                  const float* __restrict__ bias) {
    const int bid = blockIdx.x;
    if (bid < nb) {
        // ---- normalize 8 venue rows per CTA (one warp per row) ----
        const int row  = bid * 8 + (threadIdx.x >> 5);
        const int lane = threadIdx.x & 31;
        if (row >= rows) return;
        const float4* src = reinterpret_cast<const float4*>(venue + (size_t)row * DIM) + lane * 2;
        float4 x0 = src[0], x1 = src[1];
        float ss = x0.x*x0.x + x0.y*x0.y + x0.z*x0.z + x0.w*x0.w
                 + x1.x*x1.x + x1.y*x1.y + x1.z*x1.z + x1.w*x1.w;
        #pragma unroll
        for (int o = 16; o > 0; o >>= 1) ss += __shfl_xor_sync(0xffffffffu, ss, o);
        const float sc = fminf(1.0f, 1.0f / fmaxf(sqrtf(ss), EPSF));   // torch max_norm=1
        __nv_bfloat162 b0 = __floats2bfloat162_rn(x0.x*sc, x0.y*sc);
        __nv_bfloat162 b1 = __floats2bfloat162_rn(x0.z*sc, x0.w*sc);
        __nv_bfloat162 b2 = __floats2bfloat162_rn(x1.x*sc, x1.y*sc);
        __nv_bfloat162 b3 = __floats2bfloat162_rn(x1.z*sc, x1.w*sc);
        uint4 o4;
        o4.x = *reinterpret_cast<uint32_t*>(&b0); o4.y = *reinterpret_cast<uint32_t*>(&b1);
        o4.z = *reinterpret_cast<uint32_t*>(&b2); o4.w = *reinterpret_cast<uint32_t*>(&b3);
        reinterpret_cast<uint4*>(g_vnorm + (size_t)row * DIM)[lane] = o4;
    } else if (bid < nb + DIM) {
        // ---- Bt row ----
        const int n = bid - nb, k = threadIdx.x;
        g_Bt[n * DIM + k] = __float2bfloat16(W1[k * DIM + n]);
    } else {
        // ---- C row (bf16) ----
        __shared__ float sP[DIM];
        const int h = bid - nb - DIM, d = threadIdx.x;
        sP[d] = P[h * DIM + d];
        __syncthreads();
        float acc = 0.f;
        #pragma unroll 16
        for (int k = 0; k < DIM; ++k) acc = fmaf(sP[k], W2[k * DIM + d], acc);
        g_Cb[h * DIM + d] = __float2bfloat16(acc + bias[h * DIM + d]);
    }
}

// ---------------- TV = pack(vnorm @ W1, vnorm) — R8 proven form, occ 3 ----------------
#define GSM_A 0
#define GSM_B 33792
#define GSM_BYTES 67584

__global__ __launch_bounds__(256, 3)
void gemm_TV_kernel(int rows) {
    extern __shared__ __align__(16) char sm[];
    const int tid = threadIdx.x, lane = tid & 31, warp = tid >> 5;
    const int M0 = blockIdx.x * 64;
    const uint32_t smA = smem_u32(sm + GSM_A);
    const uint32_t smB = smem_u32(sm + GSM_B);

    // ---- A tile (64 rows of bf16 vnorm) + B chunk 0, all via cp.async ----
    #pragma unroll
    for (int s = 0; s < 8; ++s) {
        const int i = tid + s * 256;            // 0..2047
        const int row = i >> 5, j = i & 31;
        const int gr = M0 + row;
        if (gr < rows)
            cp16(smA + row * ROWB + j * 16,
                 reinterpret_cast<const char*>(g_vnorm) + (size_t)gr * DIM * 2 + j * 16);
        else
            *reinterpret_cast<uint4*>(sm + GSM_A + row * ROWB + j * 16) = make_uint4(0,0,0,0);
    }
    {
        const char* src = reinterpret_cast<const char*>(g_Bt);
        #pragma unroll
        for (int s = 0; s < 8; ++s) {
            const int i = tid + s * 256;
            const int row = i >> 5, j = i & 31;
            cp16(smB + row * ROWB + j * 16, src + row * 512 + j * 16);
        }
    }
    cp_commit();

    // warp tile 32x16: mgrp = warp>>2 (row half), ngrp = warp&3 (16-col group)
    const int qr = lane >> 2, qc = lane & 3;
    const int mgrp = warp >> 2, ngrp = warp & 3;
    const uint32_t aAddr = smA + (uint32_t)((mgrp * 32 + (lane & 15)) * ROWB + (lane >> 4) * 16);
    const uint32_t bAddr = smB + (uint32_t)((ngrp * 16 + (lane & 7) + ((lane >> 4) & 1) * 8) * ROWB
                                            + ((lane >> 3) & 1) * 16);

    #pragma unroll 1
    for (int chunk = 0; chunk < 4; ++chunk) {
        cp_wait0();
        __syncthreads();       // A + current B chunk resident

        float acc[2][2][4];
        #pragma unroll
        for (int mt = 0; mt < 2; ++mt)
            #pragma unroll
            for (int nt = 0; nt < 2; ++nt)
                #pragma unroll
                for (int i = 0; i < 4; ++i) acc[mt][nt][i] = 0.f;

        #pragma unroll 4
        for (int ks = 0; ks < 16; ++ks) {
            uint32_t af[2][4], bf[4];
            ldsm_x4(af[0], aAddr + ks * 32);
            ldsm_x4(af[1], aAddr + 16 * ROWB + ks * 32);
            ldsm_x4(bf, bAddr + ks * 32);
            #pragma unroll
            for (int mt = 0; mt < 2; ++mt)
                #pragma unroll
                for (int nt = 0; nt < 2; ++nt)
                    mma_bf16(acc[mt][nt], af[mt], bf[nt * 2], bf[nt * 2 + 1]);
        }
        __syncthreads();       // all warps done reading B before refill

        if (chunk < 3) {
            const char* src = reinterpret_cast<const char*>(g_Bt + (chunk + 1) * 64 * DIM);
            #pragma unroll
            for (int s = 0; s < 8; ++s) {
                const int i = tid + s * 256;
                const int row = i >> 5, j = i & 31;
                cp16(smB + row * ROWB + j * 16, src + row * 512 + j * 16);
            }
            cp_commit();
        }

        // ---- pack T(bf16) + vnorm(bf16 from smem A) -> g_TV; overlaps B refill ----
        #pragma unroll
        for (int mt = 0; mt < 2; ++mt) {
            const int lr0 = mgrp * 32 + mt * 16 + qr;
            #pragma unroll
            for (int nt = 0; nt < 2; ++nt) {
                const int col = chunk * 64 + ngrp * 16 + nt * 8 + 2 * qc;
                #pragma unroll
                for (int half = 0; half < 2; ++half) {
                    const int r0 = M0 + lr0 + half * 8;
                    if (r0 < rows) {
                        const uint32_t hh = *reinterpret_cast<const uint32_t*>(
                            sm + GSM_A + (lr0 + half * 8) * ROWB + col * 2);
                        __nv_bfloat162 tp = __floats2bfloat162_rn(
                            acc[mt][nt][half * 2 + 0], acc[mt][nt][half * 2 + 1]);
                        const uint32_t tpu = *reinterpret_cast<uint32_t*>(&tp);
                        uint2 st;
                        st.x = __byte_perm(tpu, hh, 0x5410);   // {T_lo, v_lo}
                        st.y = __byte_perm(tpu, hh, 0x7632);   // {T_hi, v_hi}
                        *reinterpret_cast<uint2*>(g_TV + (size_t)r0 * DIM + col) = st;
                    }
                }
            }
        }
    }
}

// ---------------- main kernel: R12 shape (grid=B, 128 thr, 2 cols/thread) + bf16 C ----------------
__global__ __launch_bounds__(128)
void geo_main_kernel(const int* __restrict__ batch_u,
                     const int* __restrict__ batch_v,
                     const int* __restrict__ batch_history,
                     const float* __restrict__ user_emb,
                     const float* __restrict__ venue_emb,
                     const float* __restrict__ a_ptr,
                     float* __restrict__ out) {
    __shared__ int   sidx[HIST];
    __shared__ float sred[12];
    __shared__ float sbc[3];

    const int b = blockIdx.x, tid = threadIdx.x, lane = tid & 31, warp = tid >> 5;
    #pragma unroll
    for (int i = tid; i < HIST; i += 128) sidx[i] = batch_history[b * HIST + i] << 8;
    __syncthreads();

    const int d0 = tid * 2;
    float den0 = 0.f, num0 = 0.f, den1 = 0.f, num1 = 0.f;
    const __nv_bfloat16* Cd = g_Cb + d0;

    #pragma unroll 1
    for (int rb = 0; rb < HIST; rb += 8) {
        #pragma unroll
        for (int i = 0; i < 8; ++i) {
            const int r = rb + i;
            const uint32_t off = (uint32_t)sidx[r] + d0;
            const uint2    tv = __ldg(reinterpret_cast<const uint2*>(g_TV + off));
            const uint32_t cc = __ldg(reinterpret_cast<const uint32_t*>(Cd + r * DIM));
            const float c0 = __uint_as_float(cc << 16);
            const float c1 = __uint_as_float(cc & 0xffff0000u);
            const float t0 = __uint_as_float(tv.x << 16);
            const float h0 = __uint_as_float(tv.x & 0xffff0000u);
            const float t1 = __uint_as_float(tv.y << 16);
            const float h1 = __uint_as_float(tv.y & 0xffff0000u);
            const float e0 = __expf(tanh_fast(t0 + c0));
            const float e1 = __expf(tanh_fast(t1 + c1));
            den0 += e0;  den1 += e1;
            num0 = fmaf(e0, h0, num0);
            num1 = fmaf(e1, h1, num1);
        }
    }

    // ---- l = num/den + a; score = || l2n(u) + l2n(l) - l2n(v) || ----
    const float a_val = a_ptr[0];
    const float lv0 = num0 / den0 + a_val;
    const float lv1 = num1 / den1 + a_val;
    const float2 uv = __ldg(reinterpret_cast<const float2*>(
        user_emb + (size_t)batch_u[b] * DIM + d0));
    const float2 vv = __ldg(reinterpret_cast<const float2*>(
        venue_emb + (size_t)batch_v[b] * DIM + d0));
    float su = uv.x*uv.x + uv.y*uv.y;
    float sv = vv.x*vv.x + vv.y*vv.y;
    float sl = lv0*lv0 + lv1*lv1;
    #pragma unroll
    for (int o = 16; o > 0; o >>= 1) {
        su += __shfl_xor_sync(0xffffffffu, su, o);
        sv += __shfl_xor_sync(0xffffffffu, sv, o);
        sl += __shfl_xor_sync(0xffffffffu, sl, o);
    }
    if (lane == 0) { sred[warp] = su; sred[4 + warp] = sv; sred[8 + warp] = sl; }
    __syncthreads();
    if (tid == 0) {
        float tu = 0.f, tv2 = 0.f, tl = 0.f;
        #pragma unroll
        for (int w = 0; w < 4; ++w) { tu += sred[w]; tv2 += sred[4 + w]; tl += sred[8 + w]; }
        sbc[0] = 1.f / fmaxf(sqrtf(tu), EPSF);
        sbc[1] = 1.f / fmaxf(sqrtf(tv2), EPSF);
        sbc[2] = 1.f / fmaxf(sqrtf(tl), EPSF);
    }
    __syncthreads();
    const float s0 = uv.x * sbc[0] + lv0 * sbc[2] - vv.x * sbc[1];
    const float s1 = uv.y * sbc[0] + lv1 * sbc[2] - vv.y * sbc[1];
    float ssq = s0 * s0 + s1 * s1;
    #pragma unroll
    for (int o = 16; o > 0; o >>= 1) ssq += __shfl_xor_sync(0xffffffffu, ssq, o);
    if (lane == 0) sred[warp] = ssq;
    __syncthreads();
    if (tid == 0) {
        float tot = 0.f;
        #pragma unroll
        for (int w = 0; w < 4; ++w) tot += sred[w];
        out[b] = sqrtf(tot);
    }
}

// ---------------- harness entry ----------------
extern "C" void kernel_launch(void* const* d_in, const int* in_sizes, int n_in,
                              void* d_out, int out_size) {
    const int*   batch_u       = (const int*)d_in[0];
    const int*   batch_v       = (const int*)d_in[1];
    const int*   batch_history = (const int*)d_in[2];
    const float* user_emb      = (const float*)d_in[5];
    const float* venue_emb     = (const float*)d_in[6];
    const float* W1            = (const float*)d_in[7];
    const float* W2            = (const float*)d_in[8];
    const float* P             = (const float*)d_in[9];
    const float* bias          = (const float*)d_in[10];
    const float* a             = (const float*)d_in[11];
    float* out = (float*)d_out;

    const int B = in_sizes[0];
    int rows = in_sizes[6] / DIM;
    if (rows > VROWS) rows = VROWS;
    const int nb = (rows + 7) / 8;

    cudaFuncSetAttribute(gemm_TV_kernel,
                         cudaFuncAttributeMaxDynamicSharedMemorySize, GSM_BYTES);

    precompute_kernel<<<nb + DIM + HIST, 256>>>(venue_emb, rows, nb, W1, P, W2, bias);
    gemm_TV_kernel<<<(rows + 63) / 64, 256, GSM_BYTES>>>(rows);
    geo_main_kernel<<<B, 128>>>(batch_u, batch_v, batch_history,
                                user_emb, venue_emb, a, out);
}

// round 15
// speedup vs baseline: 1.0846x; 1.0274x over previous
#include <cuda_runtime.h>
#include <cuda_bf16.h>
#include <cstdint>

#define DIM   256
#define HIST  200
#define VROWS 100000
#define EPSF  1e-12f
#define ROWB  528            // smem row stride bytes: (256+8) bf16

// ---------------- persistent device scratch ----------------
__device__ __nv_bfloat16 g_Bt[DIM * DIM];           // W1^T  (Bt[n][k] = W1[k][n])
__device__ float         g_C[HIST * DIM];           // P@W2 + bias (fp32)
__device__ uint32_t      g_TV[(size_t)VROWS * DIM]; // lo16=T bf16, hi16=vnorm bf16

// ---------------- helpers ----------------
__device__ __forceinline__ uint32_t smem_u32(const void* p) {
    uint32_t a;
    asm("{ .reg .u64 t; cvta.to.shared.u64 t, %1; cvt.u32.u64 %0, t; }" : "=r"(a) : "l"(p));
    return a;
}
__device__ __forceinline__ float tanh_fast(float x) {
    float y; asm("tanh.approx.f32 %0, %1;" : "=f"(y) : "f"(x)); return y;
}
__device__ __forceinline__ void ldsm_x4(uint32_t* r, uint32_t addr) {
    asm volatile("ldmatrix.sync.aligned.m8n8.x4.shared.b16 {%0,%1,%2,%3}, [%4];"
                 : "=r"(r[0]), "=r"(r[1]), "=r"(r[2]), "=r"(r[3]) : "r"(addr));
}
__device__ __forceinline__ void mma_bf16(float* d, const uint32_t* a,
                                         uint32_t b0, uint32_t b1) {
    asm volatile(
        "mma.sync.aligned.m16n8k16.row.col.f32.bf16.bf16.f32 "
        "{%0,%1,%2,%3}, {%4,%5,%6,%7}, {%8,%9}, {%0,%1,%2,%3};"
        : "+f"(d[0]), "+f"(d[1]), "+f"(d[2]), "+f"(d[3])
        : "r"(a[0]), "r"(a[1]), "r"(a[2]), "r"(a[3]), "r"(b0), "r"(b1));
}
__device__ __forceinline__ void cp16(uint32_t dst, const void* src) {
    asm volatile("cp.async.cg.shared.global [%0], [%1], 16;" :: "r"(dst), "l"(src));
}
__device__ __forceinline__ void cp_commit() { asm volatile("cp.async.commit_group;" ::: "memory"); }
__device__ __forceinline__ void cp_wait0()  { asm volatile("cp.async.wait_group 0;" ::: "memory"); }

// ---------------- small precompute: Bt + C ----------------
__global__ void precompute_kernel(const float* __restrict__ W1,
                                  const float* __restrict__ P,
                                  const float* __restrict__ W2,
                                  const float* __restrict__ bias) {
    const int bid = blockIdx.x;
    if (bid < DIM) {
        const int n = bid, k = threadIdx.x;
        g_Bt[n * DIM + k] = __float2bfloat16(W1[k * DIM + n]);
    } else {
        __shared__ float sP[DIM];
        const int h = bid - DIM, d = threadIdx.x;
        sP[d] = P[h * DIM + d];
        __syncthreads();
        float acc = 0.f;
        #pragma unroll 16
        for (int k = 0; k < DIM; ++k) acc = fmaf(sP[k], W2[k * DIM + d], acc);
        g_C[h * DIM + d] = acc + bias[h * DIM + d];
    }
}

// ---------------- fused: normalize 64 venue rows + TV = pack(vnorm@W1, vnorm) ----------------
// CTA tile 64 rows x 128-col chunks (x2). Warp tile 32x32 -> LDSM:MMA = 0.5.
// smem: A 64x528 = 33792, B 128x528 = 67584 -> 101376, occ 2.
#define GSM_A 0
#define GSM_B 33792
#define GSM_BYTES 101376

__global__ __launch_bounds__(256, 2)
void gemm_TV_kernel(const float* __restrict__ venue, int rows) {
    extern __shared__ __align__(16) char sm[];
    const int tid = threadIdx.x, lane = tid & 31, warp = tid >> 5;
    const int M0 = blockIdx.x * 64;
    const uint32_t smA = smem_u32(sm + GSM_A);
    const uint32_t smB = smem_u32(sm + GSM_B);

    // ---- issue B chunk 0 copy first (rides under the normalize head) ----
    {
        const char* src = reinterpret_cast<const char*>(g_Bt);   // n rows 0..127
        #pragma unroll
        for (int s = 0; s < 16; ++s) {
            const int i = tid + s * 256;            // 0..4095
            const int row = i >> 5, j = i & 31;
            cp16(smB + row * ROWB + j * 16, src + row * 512 + j * 16);
        }
        cp_commit();
    }

    // ---- normalize 8 rows per warp, fp32 venue -> bf16 smem A (no gmem vnorm) ----
    #pragma unroll
    for (int i = 0; i < 8; ++i) {
        const int lr  = warp * 8 + i;
        const int row = M0 + lr;
        if (row < rows) {
            const float4* src = reinterpret_cast<const float4*>(venue + (size_t)row * DIM) + lane * 2;
            float4 x0 = __ldg(src), x1 = __ldg(src + 1);
            float ss = x0.x*x0.x + x0.y*x0.y + x0.z*x0.z + x0.w*x0.w
                     + x1.x*x1.x + x1.y*x1.y + x1.z*x1.z + x1.w*x1.w;
            #pragma unroll
            for (int o = 16; o > 0; o >>= 1) ss += __shfl_xor_sync(0xffffffffu, ss, o);
            const float sc = fminf(1.0f, 1.0f / fmaxf(sqrtf(ss), EPSF));   // torch max_norm=1
            __nv_bfloat162 b0 = __floats2bfloat162_rn(x0.x*sc, x0.y*sc);
            __nv_bfloat162 b1 = __floats2bfloat162_rn(x0.z*sc, x0.w*sc);
            __nv_bfloat162 b2 = __floats2bfloat162_rn(x1.x*sc, x1.y*sc);
            __nv_bfloat162 b3 = __floats2bfloat162_rn(x1.z*sc, x1.w*sc);
            uint4 o4;
            o4.x = *reinterpret_cast<uint32_t*>(&b0); o4.y = *reinterpret_cast<uint32_t*>(&b1);
            o4.z = *reinterpret_cast<uint32_t*>(&b2); o4.w = *reinterpret_cast<uint32_t*>(&b3);
            *reinterpret_cast<uint4*>(sm + GSM_A + lr * ROWB + lane * 16) = o4;
        } else {
            *reinterpret_cast<uint4*>(sm + GSM_A + lr * ROWB + lane * 16) = make_uint4(0,0,0,0);
        }
    }
    cp_wait0();
    __syncthreads();

    // warp tile 32x32: mgrp = warp>>2 (row half), ngrp = warp&3 (32-col group)
    const int qr = lane >> 2, qc = lane & 3;
    const int mgrp = warp >> 2, ngrp = warp & 3;
    const uint32_t aAddr = smA + (uint32_t)((mgrp * 32 + (lane & 15)) * ROWB + (lane >> 4) * 16);
    const uint32_t bAddr = smB + (uint32_t)((ngrp * 32 + (lane & 7) + ((lane >> 4) & 1) * 8) * ROWB
                                            + ((lane >> 3) & 1) * 16);

    #pragma unroll 1
    for (int chunk = 0; chunk < 2; ++chunk) {
        float acc[2][4][4];
        #pragma unroll
        for (int mt = 0; mt < 2; ++mt)
            #pragma unroll
            for (int nt = 0; nt < 4; ++nt)
                #pragma unroll
                for (int i = 0; i < 4; ++i) acc[mt][nt][i] = 0.f;

        #pragma unroll 4
        for (int ks = 0; ks < 16; ++ks) {
            uint32_t af[2][4], bf[2][4];
            ldsm_x4(af[0], aAddr + ks * 32);
            ldsm_x4(af[1], aAddr + 16 * ROWB + ks * 32);
            ldsm_x4(bf[0], bAddr + ks * 32);
            ldsm_x4(bf[1], bAddr + 16 * ROWB + ks * 32);
            #pragma unroll
            for (int mt = 0; mt < 2; ++mt)
                #pragma unroll
                for (int ng = 0; ng < 2; ++ng)
                    #pragma unroll
                    for (int nt = 0; nt < 2; ++nt)
                        mma_bf16(acc[mt][ng * 2 + nt], af[mt],
                                 bf[ng][nt * 2], bf[ng][nt * 2 + 1]);
        }
        __syncthreads();       // all warps done reading B[chunk]

        if (chunk == 0) {      // refill B with n rows 128..255; overlaps pack epilogue
            const char* src = reinterpret_cast<const char*>(g_Bt + 128 * DIM);
            #pragma unroll
            for (int s = 0; s < 16; ++s) {
                const int i = tid + s * 256;
                const int row = i >> 5, j = i & 31;
                cp16(smB + row * ROWB + j * 16, src + row * 512 + j * 16);
            }
            cp_commit();
        }

        // ---- pack T(bf16) + vnorm(bf16 from smem A) -> g_TV ----
        #pragma unroll
        for (int mt = 0; mt < 2; ++mt) {
            const int lr0 = mgrp * 32 + mt * 16 + qr;
            #pragma unroll
            for (int nn = 0; nn < 4; ++nn) {
                const int col = chunk * 128 + ngrp * 32 + nn * 8 + 2 * qc;
                #pragma unroll
                for (int half = 0; half < 2; ++half) {
                    const int r0 = M0 + lr0 + half * 8;
                    if (r0 < rows) {
                        const uint32_t hh = *reinterpret_cast<const uint32_t*>(
                            sm + GSM_A + (lr0 + half * 8) * ROWB + col * 2);
                        __nv_bfloat162 tp = __floats2bfloat162_rn(
                            acc[mt][nn][half * 2 + 0], acc[mt][nn][half * 2 + 1]);
                        const uint32_t tpu = *reinterpret_cast<uint32_t*>(&tp);
                        uint2 st;
                        st.x = __byte_perm(tpu, hh, 0x5410);   // {T_lo, v_lo}
                        st.y = __byte_perm(tpu, hh, 0x7632);   // {T_hi, v_hi}
                        *reinterpret_cast<uint2*>(g_TV + (size_t)r0 * DIM + col) = st;
                    }
                }
            }
        }
        if (chunk == 0) { cp_wait0(); __syncthreads(); }
    }
}

// ---------------- main kernel: R12 best form (grid=B, 128 thr, 2 cols/thread, fp32 C) ----------------
__global__ __launch_bounds__(128)
void geo_main_kernel(const int* __restrict__ batch_u,
                     const int* __restrict__ batch_v,
                     const int* __restrict__ batch_history,
                     const float* __restrict__ user_emb,
                     const float* __restrict__ venue_emb,
                     const float* __restrict__ a_ptr,
                     float* __restrict__ out) {
    __shared__ int   sidx[HIST];
    __shared__ float sred[12];
    __shared__ float sbc[3];

    const int b = blockIdx.x, tid = threadIdx.x, lane = tid & 31, warp = tid >> 5;
    #pragma unroll
    for (int i = tid; i < HIST; i += 128) sidx[i] = batch_history[b * HIST + i] << 8;
    __syncthreads();

    const int d0 = tid * 2;
    float den0 = 0.f, num0 = 0.f, den1 = 0.f, num1 = 0.f;
    const float* Cd = g_C + d0;

    #pragma unroll 1
    for (int rb = 0; rb < HIST; rb += 8) {
        #pragma unroll
        for (int i = 0; i < 8; ++i) {
            const int r = rb + i;
            const uint32_t off = (uint32_t)sidx[r] + d0;
            const uint2  tv = __ldg(reinterpret_cast<const uint2*>(g_TV + off));
            const float2 cc = __ldg(reinterpret_cast<const float2*>(Cd + r * DIM));
            const float t0 = __uint_as_float(tv.x << 16);
            const float h0 = __uint_as_float(tv.x & 0xffff0000u);
            const float t1 = __uint_as_float(tv.y << 16);
            const float h1 = __uint_as_float(tv.y & 0xffff0000u);
            const float e0 = __expf(tanh_fast(t0 + cc.x));
            const float e1 = __expf(tanh_fast(t1 + cc.y));
            den0 += e0;  den1 += e1;
            num0 = fmaf(e0, h0, num0);
            num1 = fmaf(e1, h1, num1);
        }
    }

    // ---- l = num/den + a; score = || l2n(u) + l2n(l) - l2n(v) || ----
    const float a_val = a_ptr[0];
    const float lv0 = num0 / den0 + a_val;
    const float lv1 = num1 / den1 + a_val;
    const float2 uv = __ldg(reinterpret_cast<const float2*>(
        user_emb + (size_t)batch_u[b] * DIM + d0));
    const float2 vv = __ldg(reinterpret_cast<const float2*>(
        venue_emb + (size_t)batch_v[b] * DIM + d0));
    float su = uv.x*uv.x + uv.y*uv.y;
    float sv = vv.x*vv.x + vv.y*vv.y;
    float sl = lv0*lv0 + lv1*lv1;
    #pragma unroll
    for (int o = 16; o > 0; o >>= 1) {
        su += __shfl_xor_sync(0xffffffffu, su, o);
        sv += __shfl_xor_sync(0xffffffffu, sv, o);
        sl += __shfl_xor_sync(0xffffffffu, sl, o);
    }
    if (lane == 0) { sred[warp] = su; sred[4 + warp] = sv; sred[8 + warp] = sl; }
    __syncthreads();
    if (tid == 0) {
        float tu = 0.f, tv2 = 0.f, tl = 0.f;
        #pragma unroll
        for (int w = 0; w < 4; ++w) { tu += sred[w]; tv2 += sred[4 + w]; tl += sred[8 + w]; }
        sbc[0] = 1.f / fmaxf(sqrtf(tu), EPSF);
        sbc[1] = 1.f / fmaxf(sqrtf(tv2), EPSF);
        sbc[2] = 1.f / fmaxf(sqrtf(tl), EPSF);
    }
    __syncthreads();
    const float s0 = uv.x * sbc[0] + lv0 * sbc[2] - vv.x * sbc[1];
    const float s1 = uv.y * sbc[0] + lv1 * sbc[2] - vv.y * sbc[1];
    float ssq = s0 * s0 + s1 * s1;
    #pragma unroll
    for (int o = 16; o > 0; o >>= 1) ssq += __shfl_xor_sync(0xffffffffu, ssq, o);
    if (lane == 0) sred[warp] = ssq;
    __syncthreads();
    if (tid == 0) {
        float tot = 0.f;
        #pragma unroll
        for (int w = 0; w < 4; ++w) tot += sred[w];
        out[b] = sqrtf(tot);
    }
}

// ---------------- harness entry ----------------
extern "C" void kernel_launch(void* const* d_in, const int* in_sizes, int n_in,
                              void* d_out, int out_size) {
    const int*   batch_u       = (const int*)d_in[0];
    const int*   batch_v       = (const int*)d_in[1];
    const int*   batch_history = (const int*)d_in[2];
    const float* user_emb      = (const float*)d_in[5];
    const float* venue_emb     = (const float*)d_in[6];
    const float* W1            = (const float*)d_in[7];
    const float* W2            = (const float*)d_in[8];
    const float* P             = (const float*)d_in[9];
    const float* bias          = (const float*)d_in[10];
    const float* a             = (const float*)d_in[11];
    float* out = (float*)d_out;

    const int B = in_sizes[0];
    int rows = in_sizes[6] / DIM;
    if (rows > VROWS) rows = VROWS;

    cudaFuncSetAttribute(gemm_TV_kernel,
                         cudaFuncAttributeMaxDynamicSharedMemorySize, GSM_BYTES);

    precompute_kernel<<<DIM + HIST, 256>>>(W1, P, W2, bias);
    gemm_TV_kernel<<<(rows + 63) / 64, 256, GSM_BYTES>>>(venue_emb, rows);
    geo_main_kernel<<<B, 128>>>(batch_u, batch_v, batch_history,
                                user_emb, venue_emb, a, out);
}

// round 16
// speedup vs baseline: 1.0961x; 1.0107x over previous
#include <cuda_runtime.h>
#include <cuda_bf16.h>
#include <cstdint>

#define DIM   256
#define HIST  200
#define VROWS 100000
#define EPSF  1e-12f
#define ROWB  528            // smem row stride bytes: (256+8) bf16

// ---------------- persistent device scratch ----------------
__device__ __nv_bfloat16 g_Bt[DIM * DIM];           // W1^T  (Bt[n][k] = W1[k][n])
__device__ float         g_C[HIST * DIM];           // P@W2 + bias (fp32)
__device__ uint32_t      g_TV[(size_t)VROWS * DIM]; // lo16=T bf16, hi16=vnorm bf16

// ---------------- helpers ----------------
__device__ __forceinline__ uint32_t smem_u32(const void* p) {
    uint32_t a;
    asm("{ .reg .u64 t; cvta.to.shared.u64 t, %1; cvt.u32.u64 %0, t; }" : "=r"(a) : "l"(p));
    return a;
}
__device__ __forceinline__ float tanh_fast(float x) {
    float y; asm("tanh.approx.f32 %0, %1;" : "=f"(y) : "f"(x)); return y;
}
__device__ __forceinline__ void ldsm_x4(uint32_t* r, uint32_t addr) {
    asm volatile("ldmatrix.sync.aligned.m8n8.x4.shared.b16 {%0,%1,%2,%3}, [%4];"
                 : "=r"(r[0]), "=r"(r[1]), "=r"(r[2]), "=r"(r[3]) : "r"(addr));
}
__device__ __forceinline__ void mma_bf16(float* d, const uint32_t* a,
                                         uint32_t b0, uint32_t b1) {
    asm volatile(
        "mma.sync.aligned.m16n8k16.row.col.f32.bf16.bf16.f32 "
        "{%0,%1,%2,%3}, {%4,%5,%6,%7}, {%8,%9}, {%0,%1,%2,%3};"
        : "+f"(d[0]), "+f"(d[1]), "+f"(d[2]), "+f"(d[3])
        : "r"(a[0]), "r"(a[1]), "r"(a[2]), "r"(a[3]), "r"(b0), "r"(b1));
}
__device__ __forceinline__ void cp16(uint32_t dst, const void* src) {
    asm volatile("cp.async.cg.shared.global [%0], [%1], 16;" :: "r"(dst), "l"(src));
}
__device__ __forceinline__ void cp_commit() { asm volatile("cp.async.commit_group;" ::: "memory"); }
__device__ __forceinline__ void cp_wait0()  { asm volatile("cp.async.wait_group 0;" ::: "memory"); }

// ---------------- small precompute: Bt (coalesced tile transpose) + C ----------------
// blocks 0..15: 64x64 transpose tiles; blocks 16..215: C rows.
__global__ void precompute_kernel(const float* __restrict__ W1,
                                  const float* __restrict__ P,
                                  const float* __restrict__ W2,
                                  const float* __restrict__ bias) {
    const int bid = blockIdx.x;
    if (bid < 16) {
        // tile (k0, n0): read W1[k0+r][n0+c] coalesced, write Bt[n0+r][k0+c] coalesced
        __shared__ float ts[64][65];
        const int k0 = (bid >> 2) * 64, n0 = (bid & 3) * 64;
        const int c = threadIdx.x & 63, rb = threadIdx.x >> 6;   // 4 rows per pass
        #pragma unroll
        for (int i = 0; i < 16; ++i) {
            const int r = i * 4 + rb;
            ts[r][c] = W1[(k0 + r) * DIM + n0 + c];
        }
        __syncthreads();
        #pragma unroll
        for (int i = 0; i < 16; ++i) {
            const int r = i * 4 + rb;                            // n index
            g_Bt[(n0 + r) * DIM + k0 + c] = __float2bfloat16(ts[c][r]);
        }
    } else {
        __shared__ float sP[DIM];
        const int h = bid - 16, d = threadIdx.x;
        sP[d] = P[h * DIM + d];
        __syncthreads();
        float acc = 0.f;
        #pragma unroll 16
        for (int k = 0; k < DIM; ++k) acc = fmaf(sP[k], W2[k * DIM + d], acc);
        g_C[h * DIM + d] = acc + bias[h * DIM + d];
    }
}

// ---------------- fused: normalize 64 venue rows + TV = pack(vnorm@W1, vnorm) ----------------
// CTA tile 64 rows x 128-col chunks (x2). Warp tile 32x32 -> LDSM:MMA = 0.5.
// smem: A 64x528 = 33792, B 128x528 = 67584 -> 101376, occ 2.
#define GSM_A 0
#define GSM_B 33792
#define GSM_BYTES 101376

__global__ __launch_bounds__(256, 2)
void gemm_TV_kernel(const float* __restrict__ venue, int rows) {
    extern __shared__ __align__(16) char sm[];
    const int tid = threadIdx.x, lane = tid & 31, warp = tid >> 5;
    const int M0 = blockIdx.x * 64;
    const uint32_t smA = smem_u32(sm + GSM_A);
    const uint32_t smB = smem_u32(sm + GSM_B);

    // ---- issue B chunk 0 copy first (rides under the normalize head) ----
    {
        const char* src = reinterpret_cast<const char*>(g_Bt);   // n rows 0..127
        #pragma unroll
        for (int s = 0; s < 16; ++s) {
            const int i = tid + s * 256;            // 0..4095
            const int row = i >> 5, j = i & 31;
            cp16(smB + row * ROWB + j * 16, src + row * 512 + j * 16);
        }
        cp_commit();
    }

    // ---- normalize 8 rows per warp, fp32 venue -> bf16 smem A (no gmem vnorm) ----
    #pragma unroll
    for (int i = 0; i < 8; ++i) {
        const int lr  = warp * 8 + i;
        const int row = M0 + lr;
        if (row < rows) {
            const float4* src = reinterpret_cast<const float4*>(venue + (size_t)row * DIM) + lane * 2;
            float4 x0 = __ldg(src), x1 = __ldg(src + 1);
            float ss = x0.x*x0.x + x0.y*x0.y + x0.z*x0.z + x0.w*x0.w
                     + x1.x*x1.x + x1.y*x1.y + x1.z*x1.z + x1.w*x1.w;
            #pragma unroll
            for (int o = 16; o > 0; o >>= 1) ss += __shfl_xor_sync(0xffffffffu, ss, o);
            const float sc = fminf(1.0f, 1.0f / fmaxf(sqrtf(ss), EPSF));   // torch max_norm=1
            __nv_bfloat162 b0 = __floats2bfloat162_rn(x0.x*sc, x0.y*sc);
            __nv_bfloat162 b1 = __floats2bfloat162_rn(x0.z*sc, x0.w*sc);
            __nv_bfloat162 b2 = __floats2bfloat162_rn(x1.x*sc, x1.y*sc);
            __nv_bfloat162 b3 = __floats2bfloat162_rn(x1.z*sc, x1.w*sc);
            uint4 o4;
            o4.x = *reinterpret_cast<uint32_t*>(&b0); o4.y = *reinterpret_cast<uint32_t*>(&b1);
            o4.z = *reinterpret_cast<uint32_t*>(&b2); o4.w = *reinterpret_cast<uint32_t*>(&b3);
            *reinterpret_cast<uint4*>(sm + GSM_A + lr * ROWB + lane * 16) = o4;
        } else {
            *reinterpret_cast<uint4*>(sm + GSM_A + lr * ROWB + lane * 16) = make_uint4(0,0,0,0);
        }
    }
    cp_wait0();
    __syncthreads();

    // warp tile 32x32: mgrp = warp>>2 (row half), ngrp = warp&3 (32-col group)
    const int qr = lane >> 2, qc = lane & 3;
    const int mgrp = warp >> 2, ngrp = warp & 3;
    const uint32_t aAddr = smA + (uint32_t)((mgrp * 32 + (lane & 15)) * ROWB + (lane >> 4) * 16);
    const uint32_t bAddr = smB + (uint32_t)((ngrp * 32 + (lane & 7) + ((lane >> 4) & 1) * 8) * ROWB
                                            + ((lane >> 3) & 1) * 16);

    #pragma unroll 1
    for (int chunk = 0; chunk < 2; ++chunk) {
        float acc[2][4][4];
        #pragma unroll
        for (int mt = 0; mt < 2; ++mt)
            #pragma unroll
            for (int nt = 0; nt < 4; ++nt)
                #pragma unroll
                for (int i = 0; i < 4; ++i) acc[mt][nt][i] = 0.f;

        #pragma unroll 4
        for (int ks = 0; ks < 16; ++ks) {
            uint32_t af[2][4], bf[2][4];
            ldsm_x4(af[0], aAddr + ks * 32);
            ldsm_x4(af[1], aAddr + 16 * ROWB + ks * 32);
            ldsm_x4(bf[0], bAddr + ks * 32);
            ldsm_x4(bf[1], bAddr + 16 * ROWB + ks * 32);
            #pragma unroll
            for (int mt = 0; mt < 2; ++mt)
                #pragma unroll
                for (int ng = 0; ng < 2; ++ng)
                    #pragma unroll
                    for (int nt = 0; nt < 2; ++nt)
                        mma_bf16(acc[mt][ng * 2 + nt], af[mt],
                                 bf[ng][nt * 2], bf[ng][nt * 2 + 1]);
        }
        __syncthreads();       // all warps done reading B[chunk]

        if (chunk == 0) {      // refill B with n rows 128..255; overlaps pack epilogue
            const char* src = reinterpret_cast<const char*>(g_Bt + 128 * DIM);
            #pragma unroll
            for (int s = 0; s < 16; ++s) {
                const int i = tid + s * 256;
                const int row = i >> 5, j = i & 31;
                cp16(smB + row * ROWB + j * 16, src + row * 512 + j * 16);
            }
            cp_commit();
        }

        // ---- pack T(bf16) + vnorm(bf16 from smem A) -> g_TV ----
        #pragma unroll
        for (int mt = 0; mt < 2; ++mt) {
            const int lr0 = mgrp * 32 + mt * 16 + qr;
            #pragma unroll
            for (int nn = 0; nn < 4; ++nn) {
                const int col = chunk * 128 + ngrp * 32 + nn * 8 + 2 * qc;
                #pragma unroll
                for (int half = 0; half < 2; ++half) {
                    const int r0 = M0 + lr0 + half * 8;
                    if (r0 < rows) {
                        const uint32_t hh = *reinterpret_cast<const uint32_t*>(
                            sm + GSM_A + (lr0 + half * 8) * ROWB + col * 2);
                        __nv_bfloat162 tp = __floats2bfloat162_rn(
                            acc[mt][nn][half * 2 + 0], acc[mt][nn][half * 2 + 1]);
                        const uint32_t tpu = *reinterpret_cast<uint32_t*>(&tp);
                        uint2 st;
                        st.x = __byte_perm(tpu, hh, 0x5410);   // {T_lo, v_lo}
                        st.y = __byte_perm(tpu, hh, 0x7632);   // {T_hi, v_hi}
                        *reinterpret_cast<uint2*>(g_TV + (size_t)r0 * DIM + col) = st;
                    }
                }
            }
        }
        if (chunk == 0) { cp_wait0(); __syncthreads(); }
    }
}

// ---------------- main kernel: R12 best form (grid=B, 128 thr, 2 cols/thread, fp32 C) ----------------
__global__ __launch_bounds__(128)
void geo_main_kernel(const int* __restrict__ batch_u,
                     const int* __restrict__ batch_v,
                     const int* __restrict__ batch_history,
                     const float* __restrict__ user_emb,
                     const float* __restrict__ venue_emb,
                     const float* __restrict__ a_ptr,
                     float* __restrict__ out) {
    __shared__ int   sidx[HIST];
    __shared__ float sred[12];
    __shared__ float sbc[3];

    const int b = blockIdx.x, tid = threadIdx.x, lane = tid & 31, warp = tid >> 5;
    #pragma unroll
    for (int i = tid; i < HIST; i += 128) sidx[i] = batch_history[b * HIST + i] << 8;
    __syncthreads();

    const int d0 = tid * 2;
    float den0 = 0.f, num0 = 0.f, den1 = 0.f, num1 = 0.f;
    const float* Cd = g_C + d0;

    #pragma unroll 1
    for (int rb = 0; rb < HIST; rb += 8) {
        #pragma unroll
        for (int i = 0; i < 8; ++i) {
            const int r = rb + i;
            const uint32_t off = (uint32_t)sidx[r] + d0;
            const uint2  tv = __ldg(reinterpret_cast<const uint2*>(g_TV + off));
            const float2 cc = __ldg(reinterpret_cast<const float2*>(Cd + r * DIM));
            const float t0 = __uint_as_float(tv.x << 16);
            const float h0 = __uint_as_float(tv.x & 0xffff0000u);
            const float t1 = __uint_as_float(tv.y << 16);
            const float h1 = __uint_as_float(tv.y & 0xffff0000u);
            const float e0 = __expf(tanh_fast(t0 + cc.x));
            const float e1 = __expf(tanh_fast(t1 + cc.y));
            den0 += e0;  den1 += e1;
            num0 = fmaf(e0, h0, num0);
            num1 = fmaf(e1, h1, num1);
        }
    }

    // ---- l = num/den + a; score = || l2n(u) + l2n(l) - l2n(v) || ----
    const float a_val = a_ptr[0];
    const float lv0 = num0 / den0 + a_val;
    const float lv1 = num1 / den1 + a_val;
    const float2 uv = __ldg(reinterpret_cast<const float2*>(
        user_emb + (size_t)batch_u[b] * DIM + d0));
    const float2 vv = __ldg(reinterpret_cast<const float2*>(
        venue_emb + (size_t)batch_v[b] * DIM + d0));
    float su = uv.x*uv.x + uv.y*uv.y;
    float sv = vv.x*vv.x + vv.y*vv.y;
    float sl = lv0*lv0 + lv1*lv1;
    #pragma unroll
    for (int o = 16; o > 0; o >>= 1) {
        su += __shfl_xor_sync(0xffffffffu, su, o);
        sv += __shfl_xor_sync(0xffffffffu, sv, o);
        sl += __shfl_xor_sync(0xffffffffu, sl, o);
    }
    if (lane == 0) { sred[warp] = su; sred[4 + warp] = sv; sred[8 + warp] = sl; }
    __syncthreads();
    if (tid == 0) {
        float tu = 0.f, tv2 = 0.f, tl = 0.f;
        #pragma unroll
        for (int w = 0; w < 4; ++w) { tu += sred[w]; tv2 += sred[4 + w]; tl += sred[8 + w]; }
        sbc[0] = 1.f / fmaxf(sqrtf(tu), EPSF);
        sbc[1] = 1.f / fmaxf(sqrtf(tv2), EPSF);
        sbc[2] = 1.f / fmaxf(sqrtf(tl), EPSF);
    }
    __syncthreads();
    const float s0 = uv.x * sbc[0] + lv0 * sbc[2] - vv.x * sbc[1];
    const float s1 = uv.y * sbc[0] + lv1 * sbc[2] - vv.y * sbc[1];
    float ssq = s0 * s0 + s1 * s1;
    #pragma unroll
    for (int o = 16; o > 0; o >>= 1) ssq += __shfl_xor_sync(0xffffffffu, ssq, o);
    if (lane == 0) sred[warp] = ssq;
    __syncthreads();
    if (tid == 0) {
        float tot = 0.f;
        #pragma unroll
        for (int w = 0; w < 4; ++w) tot += sred[w];
        out[b] = sqrtf(tot);
    }
}

// ---------------- harness entry ----------------
extern "C" void kernel_launch(void* const* d_in, const int* in_sizes, int n_in,
                              void* d_out, int out_size) {
    const int*   batch_u       = (const int*)d_in[0];
    const int*   batch_v       = (const int*)d_in[1];
    const int*   batch_history = (const int*)d_in[2];
    const float* user_emb      = (const float*)d_in[5];
    const float* venue_emb     = (const float*)d_in[6];
    const float* W1            = (const float*)d_in[7];
    const float* W2            = (const float*)d_in[8];
    const float* P             = (const float*)d_in[9];
    const float* bias          = (const float*)d_in[10];
    const float* a             = (const float*)d_in[11];
    float* out = (float*)d_out;

    const int B = in_sizes[0];
    int rows = in_sizes[6] / DIM;
    if (rows > VROWS) rows = VROWS;

    cudaFuncSetAttribute(gemm_TV_kernel,
                         cudaFuncAttributeMaxDynamicSharedMemorySize, GSM_BYTES);

    precompute_kernel<<<16 + HIST, 256>>>(W1, P, W2, bias);
    gemm_TV_kernel<<<(rows + 63) / 64, 256, GSM_BYTES>>>(venue_emb, rows);
    geo_main_kernel<<<B, 128>>>(batch_u, batch_v, batch_history,
                                user_emb, venue_emb, a, out);
}